// round 4
// baseline (speedup 1.0000x reference)
#include <cuda_runtime.h>
#include <math.h>

#define BB   2048
#define U1N  101
#define DN   128
#define STEPN 165
#define HN   200   // hidden
#define IM1  63    // i-1

// scratch: per-batch fused bias vector base[b] (200)
__device__ float g_base[BB * HN];
__device__ int   g_mask_is_i32;

// ---------------------------------------------------------------------------
__global__ void flag_init_kernel() { g_mask_is_i32 = 1; }

// int32 layout <=> every word is 0 or 1. Byte-packed random 0/1 mask gives
// words with multiple nonzero bytes almost surely -> flag cleared.
__global__ __launch_bounds__(256) void mask_detect_kernel(const unsigned* __restrict__ m)
{
    int n = (BB * U1N) / 4;                 // safe under both layouts
    for (int idx = blockIdx.x * 256 + threadIdx.x; idx < n; idx += gridDim.x * 256) {
        if (m[idx] > 1u) { atomicExch(&g_mask_is_i32, 0); return; }
    }
}

// ---------------------------------------------------------------------------
// Kernel 1: per-b reductions + step_context + base
//   mean_emb   = mean_t emb[b,t,:]           (t=0..164)
//   mean_hist  = mean emb[b,101..163,:]
//   mean_sel   = mean gathered rows (flat idx b*63+seq, cross-batch on purpose)
//   incoming   = emb[b,164,:]
//   step_ctx   = [mean_sel|mean_hist] @ W_sc + b_sc
//   base[b,o]  = b1[o] + 0.5*W1[1,o] + inc@W1[2:130] + sc@W1[258:386] + me@W1[386:514]
// ---------------------------------------------------------------------------
__global__ __launch_bounds__(256) void prep_kernel(
    const float* __restrict__ emb, const float* __restrict__ W_sc,
    const float* __restrict__ b_sc, const float* __restrict__ W1,
    const float* __restrict__ b1, const int* __restrict__ seq)
{
    int b   = blockIdx.x;
    int tid = threadIdx.x;
    int d   = tid & 127;
    int h   = tid >> 7;          // 0 or 1: split reduction work

    __shared__ float p_emb[2][128], p_hist[2][128], p_sel[2][128];
    __shared__ float s_minc[128], s_memb[128], s_mhist[128], s_msel[128], s_sc[128];

    const float* eb = emb + (size_t)b * STEPN * DN;

    float se = 0.f, sh = 0.f, ss = 0.f;
    #pragma unroll 4
    for (int t = h; t < STEPN; t += 2) se += eb[t * DN + d];
    #pragma unroll 4
    for (int t = 101 + h; t < 164; t += 2) sh += eb[t * DN + d];
    for (int j = h; j < IM1; j += 2) {
        int s = seq[b * IM1 + j];
        ss += emb[((size_t)b * IM1 + s) * DN + d];   // deliberate cross-batch flat gather
    }
    if (h == 0) s_minc[d] = eb[164 * DN + d];
    p_emb[h][d] = se; p_hist[h][d] = sh; p_sel[h][d] = ss;
    __syncthreads();

    if (h == 0) {
        s_memb[d]  = (p_emb[0][d]  + p_emb[1][d])  * (1.f / STEPN);
        s_mhist[d] = (p_hist[0][d] + p_hist[1][d]) * (1.f / IM1);
        s_msel[d]  = (p_sel[0][d]  + p_sel[1][d])  * (1.f / IM1);
    }
    __syncthreads();

    // step_context (output dim d, 128 threads)
    if (h == 0) {
        float a0 = 0.f, a1 = 0.f;
        #pragma unroll 4
        for (int k = 0; k < 128; k += 2) {
            a0 = fmaf(s_msel[k],     W_sc[(k)     * 128 + d], a0);
            a1 = fmaf(s_msel[k + 1], W_sc[(k + 1) * 128 + d], a1);
        }
        #pragma unroll 4
        for (int k = 0; k < 128; k += 2) {
            a0 = fmaf(s_mhist[k],     W_sc[(128 + k) * 128 + d], a0);
            a1 = fmaf(s_mhist[k + 1], W_sc[(129 + k) * 128 + d], a1);
        }
        s_sc[d] = a0 + a1 + b_sc[d];
    }
    __syncthreads();

    // base (output dim o, threads 0..199)
    int o = tid;
    if (o < HN) {
        float a0 = b1[o] + 0.5f * W1[HN + o];  // idx feature = i/v_size = 64/128 = 0.5
        float a1 = 0.f, a2 = 0.f, a3 = 0.f;
        #pragma unroll 2
        for (int k = 0; k < 128; k += 2) {
            a0 = fmaf(s_minc[k],     W1[(2   + k) * HN + o], a0);
            a1 = fmaf(s_minc[k + 1], W1[(3   + k) * HN + o], a1);
            a2 = fmaf(s_sc[k],       W1[(258 + k) * HN + o], a2);
            a3 = fmaf(s_sc[k + 1],   W1[(259 + k) * HN + o], a3);
        }
        #pragma unroll 2
        for (int k = 0; k < 128; k += 2) {
            a0 = fmaf(s_memb[k],     W1[(386 + k) * HN + o], a0);
            a1 = fmaf(s_memb[k + 1], W1[(387 + k) * HN + o], a1);
        }
        g_base[b * HN + o] = a0 + a1 + a2 + a3;
    }
}

// ---------------------------------------------------------------------------
// Kernel 2: main GEMM + MLP epilogue + log_softmax + argmax, one block per b.
//   pi[b,u] = relu(base[b] + w[b,u]*W1[0,:] + emb[b,u,:]@W1[130:258,:]) @ W2 + b2
// ---------------------------------------------------------------------------
__global__ __launch_bounds__(256, 2) void main_kernel(
    const float* __restrict__ emb, const float* __restrict__ w,
    const float* __restrict__ W1, const float* __restrict__ W2,
    const float* __restrict__ b2, const void* __restrict__ mask,
    float* __restrict__ out, int mode)
{
    int b    = blockIdx.x;
    int tid  = threadIdx.x;
    int lane = tid & 31;
    int wid  = tid >> 5;

    __shared__ float s_base[224], s_w1r0[224], s_w2[224];
    __shared__ float s_w[128];
    __shared__ float s_pi[128];
    __shared__ __align__(16) float s_emb[8][8][128];   // [warp][uu][k]
    __shared__ float s_lse;
    __shared__ int   s_sel;

    for (int o = tid; o < 224; o += 256) {
        s_base[o] = (o < HN) ? g_base[b * HN + o] : 0.f;
        s_w1r0[o] = (o < HN) ? W1[o]              : 0.f;
        s_w2[o]   = (o < HN) ? W2[o]              : 0.f;
    }
    for (int u = tid; u < 128; u += 256) s_w[u] = (u < U1N) ? w[b * U1N + u] : 0.f;
    __syncthreads();

    const float* W1e = W1 + 130 * HN;
    float bb2 = b2[0];

    // 13 chunks of 8 u (last has 5); round-robin over 8 warps
    for (int c = wid; c < 13; c += 8) {
        int cu = c * 8;
        int nu = min(8, U1N - cu);

        __syncwarp();   // prior chunk's readers must finish before restaging
        #pragma unroll
        for (int uu = 0; uu < 8; ++uu) {
            if (uu < nu) {
                const float4* src =
                    (const float4*)(emb + ((size_t)b * STEPN + (cu + uu)) * DN);
                ((float4*)&s_emb[wid][uu][0])[lane] = src[lane];
            }
        }
        __syncwarp();

        float acc[8][7];
        #pragma unroll
        for (int uu = 0; uu < 8; ++uu) {
            float wu = s_w[cu + uu];
            #pragma unroll
            for (int j = 0; j < 7; ++j) {
                int o = lane + 32 * j;
                acc[uu][j] = s_base[o] + wu * s_w1r0[o];
            }
        }

        #pragma unroll 1
        for (int k0 = 0; k0 < DN; k0 += 4) {
            float4 e[8];
            #pragma unroll
            for (int uu = 0; uu < 8; ++uu)
                e[uu] = *((const float4*)&s_emb[wid][uu][k0]);
            #pragma unroll
            for (int dk = 0; dk < 4; ++dk) {
                float w1v[7];
                const float* wrow = W1e + (size_t)(k0 + dk) * HN + lane;
                #pragma unroll
                for (int j = 0; j < 7; ++j) w1v[j] = wrow[32 * j];
                #pragma unroll
                for (int uu = 0; uu < 8; ++uu) {
                    float ev = (dk == 0) ? e[uu].x : (dk == 1) ? e[uu].y
                             : (dk == 2) ? e[uu].z : e[uu].w;
                    #pragma unroll
                    for (int j = 0; j < 7; ++j)
                        acc[uu][j] = fmaf(ev, w1v[j], acc[uu][j]);
                }
            }
        }

        // relu, second layer (dot with W2), warp reduce
        for (int uu = 0; uu < nu; ++uu) {
            float s = 0.f;
            #pragma unroll
            for (int j = 0; j < 7; ++j) {
                int o = lane + 32 * j;
                s += fmaxf(acc[uu][j], 0.f) * s_w2[o];
            }
            #pragma unroll
            for (int off = 16; off; off >>= 1)
                s += __shfl_xor_sync(0xffffffffu, s, off);
            if (lane == 0) s_pi[cu + uu] = s + bb2;
        }
    }
    __syncthreads();

    // mask (dtype-adaptive: int32 vs byte layout)
    if (tid < U1N) {
        bool mv;
        if (g_mask_is_i32)
            mv = ((const int*)mask)[b * U1N + tid] != 0;
        else
            mv = ((const unsigned char*)mask)[b * U1N + tid] != 0;
        if (mv) s_pi[tid] = -1000000.0f;
    }
    __syncthreads();

    // log_softmax + argmax (warp 0)
    if (wid == 0) {
        float mv = -3.4e38f; int mi = U1N;
        for (int u = lane; u < U1N; u += 32) {
            float v = s_pi[u];
            if (v > mv) { mv = v; mi = u; }
        }
        #pragma unroll
        for (int off = 16; off; off >>= 1) {
            float ov = __shfl_xor_sync(0xffffffffu, mv, off);
            int   oi = __shfl_xor_sync(0xffffffffu, mi, off);
            if (ov > mv || (ov == mv && oi < mi)) { mv = ov; mi = oi; }
        }
        float se = 0.f;
        for (int u = lane; u < U1N; u += 32) se += expf(s_pi[u] - mv);
        #pragma unroll
        for (int off = 16; off; off >>= 1)
            se += __shfl_xor_sync(0xffffffffu, se, off);
        if (lane == 0) { s_lse = mv + logf(se); s_sel = mi; }
    }
    __syncthreads();

    float lse = s_lse;
    if (mode == 0) {                 // p only
        for (int u = tid; u < U1N; u += 256)
            out[b * U1N + u] = s_pi[u] - lse;
    } else if (mode == 1) {          // [selected (as float) | p]
        if (tid == 0) out[b] = (float)s_sel;
        float* op = out + BB;
        for (int u = tid; u < U1N; u += 256)
            op[b * U1N + u] = s_pi[u] - lse;
    } else {                         // selected only (int32)
        if (tid == 0) ((int*)out)[b] = s_sel;
    }
}

// ---------------------------------------------------------------------------
extern "C" void kernel_launch(void* const* d_in, const int* in_sizes, int n_in,
                              void* d_out, int out_size)
{
    const float* emb  = (const float*)d_in[0];   // (B, STEP, D)
    const float* w    = (const float*)d_in[1];   // (B, U1)
    const float* W_sc = (const float*)d_in[2];   // (256, 128)
    const float* b_sc = (const float*)d_in[3];   // (128)
    const float* W1   = (const float*)d_in[4];   // (514, 200)
    const float* b1   = (const float*)d_in[5];   // (200)
    const float* W2   = (const float*)d_in[6];   // (200, 1)
    const float* b2   = (const float*)d_in[7];   // (1)
    const int*   seq  = (const int*)d_in[8];     // (B, 63)
    const void*  mask = d_in[9];                 // (B, U1) bool (byte or i32)

    int mode = 1;                                  // default: selected + p
    if (out_size == BB * U1N) mode = 0;            // p only
    else if (out_size == BB)  mode = 2;            // selected only

    flag_init_kernel<<<1, 1>>>();
    mask_detect_kernel<<<208, 256>>>((const unsigned*)mask);
    prep_kernel<<<BB, 256>>>(emb, W_sc, b_sc, W1, b1, seq);
    main_kernel<<<BB, 256>>>(emb, w, W1, W2, b2, mask, (float*)d_out, mode);
}

// round 5
// speedup vs baseline: 1.1158x; 1.1158x over previous
#include <cuda_runtime.h>
#include <math.h>

#define BB    2048
#define U1N   101
#define DN    128
#define STEPN 165
#define HN    200    // hidden
#define IM1   63     // i-1
#define UPW   13     // u-rows per warp (8 warps x 13 = 104 >= 101)
#define NUP   7      // u-pairs per warp (14 slots, last is pad)

// scratch: per-batch fused bias vector base[b] (200)
__device__ float g_base[BB * HN];
__device__ int   g_mask_is_i32;

// f32x2 packed helpers (sm_100+; ptxas never emits these from C++)
#define FMA2(d, a, b) \
    asm("fma.rn.f32x2 %0, %1, %2, %0;" : "+l"(d) : "l"(a), "l"(b))
#define PACK2(d, lo, hi) \
    asm("mov.b64 %0, {%1, %2};" : "=l"(d) : "f"(lo), "f"(hi))
#define UNPACK2(lo, hi, d) \
    asm("mov.b64 {%0, %1}, %2;" : "=f"(lo), "=f"(hi) : "l"(d))

// ---------------------------------------------------------------------------
__global__ void flag_init_kernel() { g_mask_is_i32 = 1; }

__global__ __launch_bounds__(256) void mask_detect_kernel(const unsigned* __restrict__ m)
{
    int n = (BB * U1N) / 4;
    for (int idx = blockIdx.x * 256 + threadIdx.x; idx < n; idx += gridDim.x * 256) {
        if (m[idx] > 1u) { atomicExch(&g_mask_is_i32, 0); return; }
    }
}

// ---------------------------------------------------------------------------
// Kernel 1: per-b reductions + step_context + base.  512 threads, 4-way split.
// ---------------------------------------------------------------------------
__global__ __launch_bounds__(512) void prep_kernel(
    const float* __restrict__ emb, const float* __restrict__ W_sc,
    const float* __restrict__ b_sc, const float* __restrict__ W1,
    const float* __restrict__ b1, const int* __restrict__ seq)
{
    int b   = blockIdx.x;
    int tid = threadIdx.x;
    int d   = tid & 127;
    int h   = tid >> 7;          // 0..3

    __shared__ float p_emb[4][128], p_hist[4][128], p_sel[4][128];
    __shared__ float s_minc[128], s_memb[128], s_mhist[128], s_msel[128], s_sc[128];

    const float* eb = emb + (size_t)b * STEPN * DN;

    float se = 0.f, sh = 0.f, ss = 0.f;
    #pragma unroll 8
    for (int t = h; t < STEPN; t += 4) se += eb[t * DN + d];
    #pragma unroll 4
    for (int t = 101 + h; t < 164; t += 4) sh += eb[t * DN + d];
    #pragma unroll 2
    for (int j = h; j < IM1; j += 4) {
        int s = seq[b * IM1 + j];
        ss += emb[((size_t)b * IM1 + s) * DN + d];   // deliberate cross-batch flat gather
    }
    if (h == 0) s_minc[d] = eb[164 * DN + d];
    p_emb[h][d] = se; p_hist[h][d] = sh; p_sel[h][d] = ss;
    __syncthreads();

    if (h == 0) {
        s_memb[d]  = (p_emb[0][d]  + p_emb[1][d]  + p_emb[2][d]  + p_emb[3][d])  * (1.f / STEPN);
        s_mhist[d] = (p_hist[0][d] + p_hist[1][d] + p_hist[2][d] + p_hist[3][d]) * (1.f / IM1);
        s_msel[d]  = (p_sel[0][d]  + p_sel[1][d]  + p_sel[2][d]  + p_sel[3][d])  * (1.f / IM1);
    }
    __syncthreads();

    // step_context (output dim d, 128 threads)
    if (h == 0) {
        float a0 = 0.f, a1 = 0.f;
        #pragma unroll 4
        for (int k = 0; k < 128; k += 2) {
            a0 = fmaf(s_msel[k],     W_sc[(k)     * 128 + d], a0);
            a1 = fmaf(s_msel[k + 1], W_sc[(k + 1) * 128 + d], a1);
        }
        #pragma unroll 4
        for (int k = 0; k < 128; k += 2) {
            a0 = fmaf(s_mhist[k],     W_sc[(128 + k) * 128 + d], a0);
            a1 = fmaf(s_mhist[k + 1], W_sc[(129 + k) * 128 + d], a1);
        }
        s_sc[d] = a0 + a1 + b_sc[d];
    }
    __syncthreads();

    // base (output dim o, threads 0..199)
    int o = tid;
    if (o < HN) {
        float a0 = b1[o] + 0.5f * W1[HN + o];  // idx feature = 64/128 = 0.5
        float a1 = 0.f, a2 = 0.f, a3 = 0.f;
        #pragma unroll 2
        for (int k = 0; k < 128; k += 2) {
            a0 = fmaf(s_minc[k],     W1[(2   + k) * HN + o], a0);
            a1 = fmaf(s_minc[k + 1], W1[(3   + k) * HN + o], a1);
            a2 = fmaf(s_sc[k],       W1[(258 + k) * HN + o], a2);
            a3 = fmaf(s_sc[k + 1],   W1[(259 + k) * HN + o], a3);
        }
        #pragma unroll 2
        for (int k = 0; k < 128; k += 2) {
            a0 = fmaf(s_memb[k],     W1[(386 + k) * HN + o], a0);
            a1 = fmaf(s_memb[k + 1], W1[(387 + k) * HN + o], a1);
        }
        g_base[b * HN + o] = a0 + a1 + a2 + a3;
    }
}

// ---------------------------------------------------------------------------
// Kernel 2: pi[b,u] = relu(base + w*W1r0 + emb_u @ W1e) @ W2 + b2, then
// mask + log_softmax + argmax.  One block per b, 8 warps, 13 u per warp,
// f32x2 packed FMA (pairs over u), k processed in two halves of 64 with
// transposed e-staging in smem.
// ---------------------------------------------------------------------------
__global__ __launch_bounds__(256, 1) void main_kernel(
    const float* __restrict__ emb, const float* __restrict__ w,
    const float* __restrict__ W1, const float* __restrict__ W2,
    const float* __restrict__ b2, const void* __restrict__ mask,
    float* __restrict__ out, int mode)
{
    int b    = blockIdx.x;
    int tid  = threadIdx.x;
    int lane = tid & 31;
    int wid  = tid >> 5;

    __shared__ float s_base[224], s_w1r0[224], s_w2[224];
    __shared__ float s_w[112];
    __shared__ float s_pi[128];
    __shared__ __align__(8) float2 s_eT[8][64][NUP];   // [warp][k-half][u-pair]
    __shared__ float s_lse;
    __shared__ int   s_sel;

    for (int o = tid; o < 224; o += 256) {
        s_base[o] = (o < HN) ? g_base[b * HN + o] : 0.f;
        s_w1r0[o] = (o < HN) ? W1[o]              : 0.f;
        s_w2[o]   = (o < HN) ? W2[o]              : 0.f;
    }
    for (int u = tid; u < 112; u += 256) s_w[u] = (u < U1N) ? w[b * U1N + u] : 0.f;
    __syncthreads();

    const float* W1e = W1 + 130 * HN;
    float bb2 = b2[0];
    int u0 = wid * UPW;                 // this warp's first u (0,13,...,91)

    // init accumulators: acc[up][j] packs (u = u0+2up, u0+2up+1), o = lane+32j
    unsigned long long acc[NUP][7];
    #pragma unroll
    for (int up = 0; up < NUP; ++up) {
        float w_lo = s_w[u0 + 2 * up];
        float w_hi = s_w[u0 + 2 * up + 1];
        #pragma unroll
        for (int j = 0; j < 7; ++j) {
            int o = lane + 32 * j;
            float i_lo = s_base[o] + w_lo * s_w1r0[o];
            float i_hi = s_base[o] + w_hi * s_w1r0[o];
            PACK2(acc[up][j], i_lo, i_hi);
        }
    }

    // two k-halves of 64
    for (int h0 = 0; h0 < DN; h0 += 64) {
        // stage transposed e pairs: s_eT[wid][k][up] = (emb[u0+2up][h0+k], emb[u0+2up+1][h0+k])
        __syncwarp();
        #pragma unroll
        for (int ul = 0; ul < 14; ++ul) {
            const float2 ev = *(const float2*)(emb +
                ((size_t)b * STEPN + (u0 + ul)) * DN + h0 + 2 * lane);
            float* dst = (ul & 1) ? &s_eT[wid][2 * lane][ul >> 1].y
                                  : &s_eT[wid][2 * lane][ul >> 1].x;
            dst[0]           = ev.x;
            dst[2 * NUP]     = ev.y;     // next k slot: stride NUP float2 = 2*NUP floats
        }
        __syncwarp();

        const float* wbase = W1e + (size_t)h0 * HN + lane;
        #pragma unroll 2
        for (int k = 0; k < 64; ++k) {
            unsigned long long ep[NUP];
            #pragma unroll
            for (int up = 0; up < NUP; ++up)
                ep[up] = *(const unsigned long long*)&s_eT[wid][k][up];

            const float* wrow = wbase + (size_t)k * HN;
            float wv[7];
            #pragma unroll
            for (int j = 0; j < 7; ++j) wv[j] = __ldg(wrow + 32 * j);

            #pragma unroll
            for (int j = 0; j < 7; ++j) {
                unsigned long long wd;
                PACK2(wd, wv[j], wv[j]);
                #pragma unroll
                for (int up = 0; up < NUP; ++up)
                    FMA2(acc[up][j], ep[up], wd);
            }
        }
    }

    // epilogue: relu, dot W2, warp reduce; write 13 pi values per warp
    #pragma unroll
    for (int up = 0; up < NUP; ++up) {
        float s0 = 0.f, s1 = 0.f;
        #pragma unroll
        for (int j = 0; j < 7; ++j) {
            float a_lo, a_hi;
            UNPACK2(a_lo, a_hi, acc[up][j]);
            float w2v = s_w2[lane + 32 * j];
            s0 += fmaxf(a_lo, 0.f) * w2v;
            s1 += fmaxf(a_hi, 0.f) * w2v;
        }
        #pragma unroll
        for (int off = 16; off; off >>= 1) {
            s0 += __shfl_xor_sync(0xffffffffu, s0, off);
            s1 += __shfl_xor_sync(0xffffffffu, s1, off);
        }
        if (lane == 0) {
            int ue = u0 + 2 * up, uo = ue + 1;
            if (ue < U1N) s_pi[ue] = s0 + bb2;
            if (uo < U1N && (2 * up + 1) < UPW) s_pi[uo] = s1 + bb2;
        }
    }
    __syncthreads();

    // mask (dtype-adaptive: int32 vs byte layout)
    if (tid < U1N) {
        bool mv;
        if (g_mask_is_i32)
            mv = ((const int*)mask)[b * U1N + tid] != 0;
        else
            mv = ((const unsigned char*)mask)[b * U1N + tid] != 0;
        if (mv) s_pi[tid] = -1000000.0f;
    }
    __syncthreads();

    // log_softmax + argmax (warp 0)
    if (wid == 0) {
        float mv = -3.4e38f; int mi = U1N;
        for (int u = lane; u < U1N; u += 32) {
            float v = s_pi[u];
            if (v > mv) { mv = v; mi = u; }
        }
        #pragma unroll
        for (int off = 16; off; off >>= 1) {
            float ov = __shfl_xor_sync(0xffffffffu, mv, off);
            int   oi = __shfl_xor_sync(0xffffffffu, mi, off);
            if (ov > mv || (ov == mv && oi < mi)) { mv = ov; mi = oi; }
        }
        float se = 0.f;
        for (int u = lane; u < U1N; u += 32) se += expf(s_pi[u] - mv);
        #pragma unroll
        for (int off = 16; off; off >>= 1)
            se += __shfl_xor_sync(0xffffffffu, se, off);
        if (lane == 0) { s_lse = mv + logf(se); s_sel = mi; }
    }
    __syncthreads();

    float lse = s_lse;
    if (mode == 0) {                 // p only
        for (int u = tid; u < U1N; u += 256)
            out[b * U1N + u] = s_pi[u] - lse;
    } else if (mode == 1) {          // [selected (as float) | p]
        if (tid == 0) out[b] = (float)s_sel;
        float* op = out + BB;
        for (int u = tid; u < U1N; u += 256)
            op[b * U1N + u] = s_pi[u] - lse;
    } else {                         // selected only (int32)
        if (tid == 0) ((int*)out)[b] = s_sel;
    }
}

// ---------------------------------------------------------------------------
extern "C" void kernel_launch(void* const* d_in, const int* in_sizes, int n_in,
                              void* d_out, int out_size)
{
    const float* emb  = (const float*)d_in[0];   // (B, STEP, D)
    const float* w    = (const float*)d_in[1];   // (B, U1)
    const float* W_sc = (const float*)d_in[2];   // (256, 128)
    const float* b_sc = (const float*)d_in[3];   // (128)
    const float* W1   = (const float*)d_in[4];   // (514, 200)
    const float* b1   = (const float*)d_in[5];   // (200)
    const float* W2   = (const float*)d_in[6];   // (200, 1)
    const float* b2   = (const float*)d_in[7];   // (1)
    const int*   seq  = (const int*)d_in[8];     // (B, 63)
    const void*  mask = d_in[9];                 // (B, U1) bool (byte or i32)

    int mode = 1;                                  // default: selected + p
    if (out_size == BB * U1N) mode = 0;            // p only
    else if (out_size == BB)  mode = 2;            // selected only

    flag_init_kernel<<<1, 1>>>();
    mask_detect_kernel<<<208, 256>>>((const unsigned*)mask);
    prep_kernel<<<BB, 512>>>(emb, W_sc, b_sc, W1, b1, seq);
    main_kernel<<<BB, 256>>>(emb, w, W1, W2, b2, mask, (float*)d_out, mode);
}